// round 1
// baseline (speedup 1.0000x reference)
#include <cuda_runtime.h>
#include <math.h>

#define KPTS 20
#define KP3  23
#define OUT_H 64
#define OUT_W 256
#define NPIX (OUT_H*OUT_W)   // 16384
#define BATCH 128
#define IN_H 128
#define IN_W 512
#define BG 16                // batches per block in sampler

__device__ float g_inv[KP3*KP3];
__device__ float g_glift[KP3*NPIX];   // transposed: [i][n]
__device__ float g_T[BATCH*KP3*2];    // [b][i][c]

__device__ __forceinline__ void ctrl_pt(int k, double& cx, double& cy) {
    const int half = KPTS/2;
    int j = (k < half) ? k : (k - half);
    cx = 0.05 + 0.90 * ((double)j / (double)(half-1));
    cy = (k < half) ? 0.05 : 0.95;
}

// ---------------- 1. build + invert the 23x23 TPS delta matrix (f64) ----------------
__global__ void k_invdelta() {
    __shared__ double A[KP3][2*KP3];
    __shared__ int piv;
    int lane = threadIdx.x;

    if (lane < KP3) {
        int r = lane;
        for (int c = 0; c < KP3; ++c) {
            double v;
            if (r < KPTS) {
                if (c == 0) v = 1.0;
                else if (c <= 2) { double x,y; ctrl_pt(r,x,y); v = (c==1)? x : y; }
                else {
                    int k2 = c - 3;
                    if (r == k2) v = 0.0;   // d set to 1 -> 1^2*log(1) = 0
                    else {
                        double x1,y1,x2,y2; ctrl_pt(r,x1,y1); ctrl_pt(k2,x2,y2);
                        double dx=x1-x2, dy=y1-y2;
                        double d = sqrt(dx*dx+dy*dy);
                        v = d*d*log(d);
                    }
                }
            } else if (r < 22) {
                if (c < 3) v = 0.0;
                else { double x,y; ctrl_pt(c-3,x,y); v = (r==20)? x : y; }
            } else {
                v = (c < 3) ? 0.0 : 1.0;
            }
            A[r][c] = v;
            A[r][KP3+c] = (r==c) ? 1.0 : 0.0;
        }
    }
    __syncthreads();

    for (int p = 0; p < KP3; ++p) {
        if (lane == 0) {
            int best = p; double bv = fabs(A[p][p]);
            for (int r = p+1; r < KP3; ++r) {
                double v = fabs(A[r][p]);
                if (v > bv) { bv = v; best = r; }
            }
            piv = best;
        }
        __syncthreads();
        if (piv != p) {
            for (int c = lane; c < 2*KP3; c += 32) {
                double t = A[p][c]; A[p][c] = A[piv][c]; A[piv][c] = t;
            }
        }
        __syncthreads();
        double ip = 1.0 / A[p][p];
        for (int c = lane; c < 2*KP3; c += 32) A[p][c] *= ip;
        __syncthreads();
        if (lane < KP3 && lane != p) {
            double f = A[lane][p];
            #pragma unroll 4
            for (int c = 0; c < 2*KP3; ++c) A[lane][c] -= f * A[p][c];
        }
        __syncthreads();
    }
    if (lane < KP3)
        for (int c = 0; c < KP3; ++c)
            g_inv[lane*KP3+c] = (float)A[lane][KP3+c];
}

// ---------------- 2. lifted output grid G_LIFTED (transposed, f64 math) ----------------
__global__ void k_glift() {
    int n = blockIdx.x*blockDim.x + threadIdx.x;
    if (n >= NPIX) return;
    int x = n & (OUT_W-1), y = n >> 8;
    double gx = ((double)x + 0.5) / (double)OUT_W;
    double gy = ((double)y + 0.5) / (double)OUT_H;
    g_glift[0*NPIX+n] = 1.0f;
    g_glift[1*NPIX+n] = (float)gx;
    g_glift[2*NPIX+n] = (float)gy;
    #pragma unroll
    for (int k = 0; k < KPTS; ++k) {
        double cx, cy; ctrl_pt(k, cx, cy);
        double dx = gx-cx, dy = gy-cy;
        double d = sqrt(dx*dx+dy*dy);
        g_glift[(3+k)*NPIX+n] = (float)(d*d*log(d+1e-6));
    }
}

// ---------------- 3. per-batch TPS coefficients T = inv_delta @ [ctrl;0] ----------------
__global__ void k_T(const float* __restrict__ ctrl) {
    int b = blockIdx.x;
    __shared__ float sc[KPTS*2];
    if (threadIdx.x < KPTS*2) sc[threadIdx.x] = ctrl[b*KPTS*2 + threadIdx.x];
    __syncthreads();
    int t = threadIdx.x;
    if (t < KP3*2) {
        int i = t >> 1, c = t & 1;
        float acc = 0.f;
        #pragma unroll
        for (int j = 0; j < KPTS; ++j)
            acc = fmaf(g_inv[i*KP3+j], sc[j*2+c], acc);
        g_T[b*KP3*2 + t] = acc;
    }
}

// ---------------- 4. grid eval + bilinear sampling ----------------
__global__ __launch_bounds__(OUT_W) void k_sample(const float* __restrict__ X,
                                                  float* __restrict__ out) {
    int y  = blockIdx.x;           // 0..63
    int b0 = blockIdx.y * BG;      // batch group
    int x  = threadIdx.x;          // 0..255
    int n  = y*OUT_W + x;

    __shared__ float Ts[BG*KP3*2];
    for (int t = threadIdx.x; t < BG*KP3*2; t += blockDim.x)
        Ts[t] = g_T[b0*KP3*2 + t];

    float gl[KP3];
    #pragma unroll
    for (int i = 0; i < KP3; ++i) gl[i] = g_glift[i*NPIX + n];
    __syncthreads();

    #pragma unroll 2
    for (int bb = 0; bb < BG; ++bb) {
        int b = b0 + bb;
        const float* tb = &Ts[bb*KP3*2];
        float gpx = 0.f, gpy = 0.f;
        #pragma unroll
        for (int i = 0; i < KP3; ++i) {
            gpx = fmaf(gl[i], tb[2*i],   gpx);
            gpy = fmaf(gl[i], tb[2*i+1], gpy);
        }
        float Gx = fminf(fmaxf((float)IN_W * gpx, 0.f), (float)(IN_W-2));
        float Gy = fminf(fmaxf((float)IN_H * gpy, 0.f), (float)(IN_H-2));
        float fx0 = floorf(Gx), fy0 = floorf(Gy);
        int x0 = (int)fx0, y0 = (int)fy0;

        const float* p0 = X + (((size_t)b*IN_H + y0)*IN_W + x0)*3;
        const float* p1 = p0 + IN_W*3;

        float ax = Gx - fx0, bx = fx0 + 1.f - Gx;
        float ay = Gy - fy0, by = fy0 + 1.f - Gy;
        float w00 = bx*by, w01 = bx*ay, w10 = ax*by, w11 = ax*ay;

        float i00x=p0[0], i00y=p0[1], i00z=p0[2];
        float i10x=p0[3], i10y=p0[4], i10z=p0[5];
        float i01x=p1[0], i01y=p1[1], i01z=p1[2];
        float i11x=p1[3], i11y=p1[4], i11z=p1[5];

        float* o = out + (((size_t)b*OUT_H + y)*OUT_W + x)*3;
        o[0] = w00*i00x + w01*i01x + w10*i10x + w11*i11x;
        o[1] = w00*i00y + w01*i01y + w10*i10y + w11*i11y;
        o[2] = w00*i00z + w01*i01z + w10*i10z + w11*i11z;
    }
}

extern "C" void kernel_launch(void* const* d_in, const int* in_sizes, int n_in,
                              void* d_out, int out_size) {
    const float* X    = (const float*)d_in[0];
    const float* ctrl = (const float*)d_in[1];
    // defensive: if metadata order differs, swap by size
    if (n_in >= 2 && in_sizes[0] == BATCH*KPTS*2) {
        X    = (const float*)d_in[1];
        ctrl = (const float*)d_in[0];
    }
    float* out = (float*)d_out;

    k_invdelta<<<1, 32>>>();
    k_glift<<<NPIX/256, 256>>>();
    k_T<<<BATCH, 64>>>(ctrl);
    dim3 grid(OUT_H, BATCH/BG);
    k_sample<<<grid, OUT_W>>>(X, out);
}

// round 2
// speedup vs baseline: 1.5289x; 1.5289x over previous
#include <cuda_runtime.h>
#include <math.h>

#define KPTS 20
#define KP3  23
#define OUT_H 64
#define OUT_W 256
#define NPIX (OUT_H*OUT_W)   // 16384
#define BATCH 128
#define IN_H 128
#define IN_W 512
#define BG 8                 // batches per block in sampler

__device__ float g_inv[KP3*KP3];
__device__ float g_glift[KP3*NPIX];   // transposed: [i][n]
__device__ float g_T[BATCH*KP3*2];    // [b][i][c]

__device__ __forceinline__ void ctrl_pt(int k, double& cx, double& cy) {
    const int half = KPTS/2;
    int j = (k < half) ? k : (k - half);
    double step = (0.95 - 0.05) / 9.0;              // match numpy linspace
    cx = (j == 9) ? 0.95 : 0.05 + (double)j * step;
    cy = (k < half) ? 0.05 : 0.95;
}

// ======================= double-single (float-float) helpers =======================
struct DS { float h, l; };

__device__ __forceinline__ DS ds_norm(float h, float l) {   // fast_two_sum
    float s = h + l;
    float e = l - (s - h);
    return {s, e};
}
__device__ __forceinline__ DS ds_add(DS a, DS b) {
    float s = a.h + b.h;
    float v = s - a.h;
    float e = (a.h - (s - v)) + (b.h - v);
    e += a.l + b.l;
    return ds_norm(s, e);
}
__device__ __forceinline__ DS ds_mul(DS a, DS b) {
    float p = a.h * b.h;
    float e = fmaf(a.h, b.h, -p);
    e = fmaf(a.h, b.l, e);
    e = fmaf(a.l, b.h, e);
    return ds_norm(p, e);
}
__device__ __forceinline__ DS ds_div(DS a, DS b) {
    float q = a.h / b.h;
    float p = q * b.h;
    float pe = fmaf(q, b.h, -p);
    float s = a.h - p;
    float v = s - a.h;
    float e = (a.h - (s - v)) + ((-p) - v);
    e += a.l - pe - q * b.l;
    float ql = (s + e) / b.h;
    return ds_norm(q, ql);
}
__device__ __forceinline__ DS ds_sqrt(DS t) {
    float y = sqrtf(t.h);
    float p = y * y;
    float pe = fmaf(y, y, -p);
    float s = t.h - p;
    float v = s - t.h;
    float e = (t.h - (s - v)) + ((-p) - v);
    e += t.l - pe;
    float corr = (s + e) / (2.0f * y);
    return ds_norm(y, corr);
}
// natural log of a DS value in (0, 2], accuracy ~2^-45
__device__ __forceinline__ DS ds_log(DS a) {
    int ix = __float_as_int(a.h);
    int e = ((ix >> 23) & 0xFF) - 127;
    float sc = __int_as_float((127 - e) << 23);   // exact 2^-e
    float mh = a.h * sc;                           // [1,2)
    float ml = a.l * sc;
    if (mh > 1.41421356f) { mh *= 0.5f; ml *= 0.5f; e += 1; }
    DS r = ds_norm(mh - 1.0f, ml);                 // mh-1 exact (Sterbenz)
    DS den = ds_add({2.0f, 0.0f}, r);
    DS s = ds_div(r, den);                         // |s| <= 0.1716
    float z = s.h * s.h;
    float c = fmaf(z, 0.15384615f, 0.18181818f);   // 2/13, 2/11
    c = fmaf(z, c, 0.22222222f);                   // 2/9
    c = fmaf(z, c, 0.28571429f);                   // 2/7
    c = fmaf(z, c, 0.4f);                          // 2/5
    c = fmaf(z, c, 0.66666667f);                   // 2/3
    c *= z;
    DS logm = ds_add({2.0f * s.h, 2.0f * s.l}, {s.h * c, 0.0f});
    float fe = (float)e;
    DS elog2 = {fe * 0.693145751953125f, fe * 1.4286068203094172e-06f};
    return ds_add(elog2, logm);
}

// ---------------- 1. build + invert the 23x23 TPS delta matrix (f64) ----------------
__global__ void k_invdelta() {
    __shared__ double A[KP3][2*KP3];
    int lane = threadIdx.x;

    if (lane < KP3) {
        int r = lane;
        for (int c = 0; c < KP3; ++c) {
            double v;
            if (r < KPTS) {
                if (c == 0) v = 1.0;
                else if (c <= 2) { double x,y; ctrl_pt(r,x,y); v = (c==1)? x : y; }
                else {
                    int k2 = c - 3;
                    if (r == k2) v = 0.0;
                    else {
                        double x1,y1,x2,y2; ctrl_pt(r,x1,y1); ctrl_pt(k2,x2,y2);
                        double dx=x1-x2, dy=y1-y2;
                        double d = sqrt(dx*dx+dy*dy);
                        v = d*d*log(d);
                    }
                }
            } else if (r < 22) {
                if (c < 3) v = 0.0;
                else { double x,y; ctrl_pt(c-3,x,y); v = (r==20)? x : y; }
            } else {
                v = (c < 3) ? 0.0 : 1.0;
            }
            A[r][c] = v;
            A[r][KP3+c] = (r==c) ? 1.0 : 0.0;
        }
    }
    __syncwarp();

    for (int p = 0; p < KP3; ++p) {
        // warp-parallel partial-pivot search
        double pv = (lane >= p && lane < KP3) ? fabs(A[lane][p]) : -1.0;
        int    pi = lane;
        #pragma unroll
        for (int off = 16; off; off >>= 1) {
            double ov = __shfl_down_sync(0xFFFFFFFFu, pv, off);
            int    oi = __shfl_down_sync(0xFFFFFFFFu, pi, off);
            if (ov > pv) { pv = ov; pi = oi; }
        }
        int piv = __shfl_sync(0xFFFFFFFFu, pi, 0);
        if (piv != p) {
            for (int c = lane; c < 2*KP3; c += 32) {
                double t = A[p][c]; A[p][c] = A[piv][c]; A[piv][c] = t;
            }
        }
        __syncwarp();
        double ip = 1.0 / A[p][p];
        for (int c = lane; c < 2*KP3; c += 32) A[p][c] *= ip;
        __syncwarp();
        if (lane < KP3 && lane != p) {
            double f = A[lane][p];
            #pragma unroll 4
            for (int c = 0; c < 2*KP3; ++c) A[lane][c] -= f * A[p][c];
        }
        __syncwarp();
    }
    if (lane < KP3)
        for (int c = 0; c < KP3; ++c)
            g_inv[lane*KP3+c] = (float)A[lane][KP3+c];
}

// ---------------- 2. lifted output grid (double-single on FP32 pipe) ----------------
__global__ void k_glift() {
    __shared__ float cxh[KPTS], cxl[KPTS], cyh[KPTS], cyl[KPTS];
    if (threadIdx.x < KPTS) {
        int k = threadIdx.x;
        double cx, cy; ctrl_pt(k, cx, cy);
        float h = (float)cx; cxh[k] = h; cxl[k] = (float)(cx - (double)h);
        float hy = (float)cy; cyh[k] = hy; cyl[k] = (float)(cy - (double)hy);
    }
    __syncthreads();

    int n = blockIdx.x*blockDim.x + threadIdx.x;
    int x = n & (OUT_W-1), y = n >> 8;
    float gx = ((float)x + 0.5f) * (1.0f/256.0f);  // exact
    float gy = ((float)y + 0.5f) * (1.0f/64.0f);   // exact
    g_glift[0*NPIX+n] = 1.0f;
    g_glift[1*NPIX+n] = gx;
    g_glift[2*NPIX+n] = gy;

    const DS EPS = {1e-6f, -1.1686097e-14f};       // DS(1e-6 double)

    #pragma unroll 4
    for (int k = 0; k < KPTS; ++k) {
        DS dx = ds_add({gx, 0.0f}, {-cxh[k], -cxl[k]});
        DS dy = ds_add({gy, 0.0f}, {-cyh[k], -cyl[k]});
        DS t  = ds_add(ds_mul(dx, dx), ds_mul(dy, dy));
        DS d  = ds_sqrt(t);
        DS lg = ds_log(ds_add(d, EPS));
        DS d2 = ds_mul(d, d);
        DS v  = ds_mul(d2, lg);
        g_glift[(3+k)*NPIX+n] = v.h;
    }
}

// ---------------- 3. per-batch TPS coefficients T = inv_delta @ [ctrl;0] ----------------
__global__ void k_T(const float* __restrict__ ctrl) {
    int b = blockIdx.x;
    __shared__ float sc[KPTS*2];
    if (threadIdx.x < KPTS*2) sc[threadIdx.x] = ctrl[b*KPTS*2 + threadIdx.x];
    __syncthreads();
    int t = threadIdx.x;
    if (t < KP3*2) {
        int i = t >> 1, c = t & 1;
        float acc = 0.f;
        #pragma unroll
        for (int j = 0; j < KPTS; ++j)
            acc = fmaf(g_inv[i*KP3+j], sc[j*2+c], acc);
        g_T[b*KP3*2 + t] = acc;
    }
}

// ---------------- 4. grid eval + bilinear sampling ----------------
__global__ __launch_bounds__(OUT_W) void k_sample(const float* __restrict__ X,
                                                  float* __restrict__ out) {
    int y  = blockIdx.x;           // 0..63
    int b0 = blockIdx.y * BG;      // batch group
    int x  = threadIdx.x;          // 0..255
    int n  = y*OUT_W + x;

    __shared__ float Ts[BG*KP3*2];
    for (int t = threadIdx.x; t < BG*KP3*2; t += blockDim.x)
        Ts[t] = g_T[b0*KP3*2 + t];

    float gl[KP3];
    #pragma unroll
    for (int i = 0; i < KP3; ++i) gl[i] = g_glift[i*NPIX + n];
    __syncthreads();

    #pragma unroll 2
    for (int bb = 0; bb < BG; ++bb) {
        int b = b0 + bb;
        const float* tb = &Ts[bb*KP3*2];
        float gpx = 0.f, gpy = 0.f;
        #pragma unroll
        for (int i = 0; i < KP3; ++i) {
            gpx = fmaf(gl[i], tb[2*i],   gpx);
            gpy = fmaf(gl[i], tb[2*i+1], gpy);
        }
        float Gx = fminf(fmaxf((float)IN_W * gpx, 0.f), (float)(IN_W-2));
        float Gy = fminf(fmaxf((float)IN_H * gpy, 0.f), (float)(IN_H-2));
        float fx0 = floorf(Gx), fy0 = floorf(Gy);
        int x0 = (int)fx0, y0 = (int)fy0;

        const float* p0 = X + (((size_t)b*IN_H + y0)*IN_W + x0)*3;
        const float* p1 = p0 + IN_W*3;

        float ax = Gx - fx0, bx = fx0 + 1.f - Gx;
        float ay = Gy - fy0, by = fy0 + 1.f - Gy;
        float w00 = bx*by, w01 = bx*ay, w10 = ax*by, w11 = ax*ay;

        float i00x=p0[0], i00y=p0[1], i00z=p0[2];
        float i10x=p0[3], i10y=p0[4], i10z=p0[5];
        float i01x=p1[0], i01y=p1[1], i01z=p1[2];
        float i11x=p1[3], i11y=p1[4], i11z=p1[5];

        float* o = out + (((size_t)b*OUT_H + y)*OUT_W + x)*3;
        o[0] = w00*i00x + w01*i01x + w10*i10x + w11*i11x;
        o[1] = w00*i00y + w01*i01y + w10*i10y + w11*i11y;
        o[2] = w00*i00z + w01*i01z + w10*i10z + w11*i11z;
    }
}

extern "C" void kernel_launch(void* const* d_in, const int* in_sizes, int n_in,
                              void* d_out, int out_size) {
    const float* X    = (const float*)d_in[0];
    const float* ctrl = (const float*)d_in[1];
    if (n_in >= 2 && in_sizes[0] == BATCH*KPTS*2) {   // defensive order swap
        X    = (const float*)d_in[1];
        ctrl = (const float*)d_in[0];
    }
    float* out = (float*)d_out;

    k_invdelta<<<1, 32>>>();
    k_glift<<<NPIX/256, 256>>>();
    k_T<<<BATCH, 64>>>(ctrl);
    dim3 grid(OUT_H, BATCH/BG);
    k_sample<<<grid, OUT_W>>>(X, out);
}

// round 4
// speedup vs baseline: 4.5763x; 2.9931x over previous
#include <cuda_runtime.h>
#include <math.h>

#define KPTS 20
#define KP3  23
#define OUT_H 64
#define OUT_W 256
#define NPIX (OUT_H*OUT_W)   // 16384
#define BATCH 128
#define IN_H 128
#define IN_W 512
#define BG 4                 // batches per block in sampler

__device__ float g_glift[KP3*NPIX];   // transposed: [i][n]
__device__ float g_T[BATCH*KP3*2];    // [b][i][c]

// ===================== compile-time INV_DELTA (constexpr f64) =====================
__host__ __device__ constexpr double cpt_x(int k) {
    int j = (k < KPTS/2) ? k : (k - KPTS/2);
    double step = (0.95 - 0.05) / 9.0;
    return (j == 9) ? 0.95 : 0.05 + (double)j * step;
}
__host__ __device__ constexpr double cpt_y(int k) { return (k < KPTS/2) ? 0.05 : 0.95; }

constexpr double csqrt(double x) {
    double y = (x > 1.0) ? x : 1.0;
    for (int i = 0; i < 40; ++i) y = 0.5 * (y + x / y);
    return y;
}
// log(x) for x in (0, 2): two sqrt reductions then atanh series
constexpr double clog(double x) {
    double r = csqrt(csqrt(x));            // x^(1/4)
    double s = (r - 1.0) / (r + 1.0);      // |s| small
    double z = s * s;
    double sum = 0.0;
    double term = s;
    for (int n = 0; n < 26; ++n) {
        sum += term / (double)(2*n + 1);
        term *= z;
    }
    return 8.0 * sum;                      // 4 * 2*atanh(s)
}

struct InvMat { float m[KP3*KP3]; };

constexpr InvMat make_inv() {
    double A[KP3][2*KP3] = {};
    for (int r = 0; r < KP3; ++r)
        for (int c = 0; c < KP3; ++c) {
            double v = 0.0;
            if (r < KPTS) {
                if (c == 0) v = 1.0;
                else if (c == 1) v = cpt_x(r);
                else if (c == 2) v = cpt_y(r);
                else {
                    int k2 = c - 3;
                    if (r == k2) v = 0.0;
                    else {
                        double dx = cpt_x(r) - cpt_x(k2);
                        double dy = cpt_y(r) - cpt_y(k2);
                        double d = csqrt(dx*dx + dy*dy);
                        v = d*d*clog(d);
                    }
                }
            } else if (r == 20) { v = (c >= 3) ? cpt_x(c-3) : 0.0; }
            else if (r == 21)   { v = (c >= 3) ? cpt_y(c-3) : 0.0; }
            else                { v = (c >= 3) ? 1.0 : 0.0; }
            A[r][c] = v;
            A[r][KP3 + c] = (r == c) ? 1.0 : 0.0;
        }
    // Gauss-Jordan with partial pivot
    for (int p = 0; p < KP3; ++p) {
        int best = p; double bv = A[p][p] < 0 ? -A[p][p] : A[p][p];
        for (int r = p+1; r < KP3; ++r) {
            double v = A[r][p] < 0 ? -A[r][p] : A[r][p];
            if (v > bv) { bv = v; best = r; }
        }
        if (best != p)
            for (int c = 0; c < 2*KP3; ++c) {
                double t = A[p][c]; A[p][c] = A[best][c]; A[best][c] = t;
            }
        double ip = 1.0 / A[p][p];
        for (int c = 0; c < 2*KP3; ++c) A[p][c] *= ip;
        for (int r = 0; r < KP3; ++r) {
            if (r == p) continue;
            double f = A[r][p];
            for (int c = 0; c < 2*KP3; ++c) A[r][c] -= f * A[p][c];
        }
    }
    InvMat out{};
    for (int r = 0; r < KP3; ++r)
        for (int c = 0; c < KP3; ++c)
            out.m[r*KP3+c] = (float)A[r][KP3+c];
    return out;
}

__device__ constexpr InvMat g_invmat = make_inv();

// ======================= double-single (float-float) helpers =======================
struct DS { float h, l; };

__device__ __forceinline__ DS ds_norm(float h, float l) {
    float s = h + l;
    float e = l - (s - h);
    return {s, e};
}
__device__ __forceinline__ DS ds_add(DS a, DS b) {
    float s = a.h + b.h;
    float v = s - a.h;
    float e = (a.h - (s - v)) + (b.h - v);
    e += a.l + b.l;
    return ds_norm(s, e);
}
__device__ __forceinline__ DS ds_mul(DS a, DS b) {
    float p = a.h * b.h;
    float e = fmaf(a.h, b.h, -p);
    e = fmaf(a.h, b.l, e);
    e = fmaf(a.l, b.h, e);
    return ds_norm(p, e);
}
__device__ __forceinline__ DS ds_div(DS a, DS b) {
    float q = a.h / b.h;
    float p = q * b.h;
    float pe = fmaf(q, b.h, -p);
    float s = a.h - p;
    float v = s - a.h;
    float e = (a.h - (s - v)) + ((-p) - v);
    e += a.l - pe - q * b.l;
    float ql = (s + e) / b.h;
    return ds_norm(q, ql);
}
__device__ __forceinline__ DS ds_sqrt(DS t) {
    float y = sqrtf(t.h);
    float p = y * y;
    float pe = fmaf(y, y, -p);
    float s = t.h - p;
    float v = s - t.h;
    float e = (t.h - (s - v)) + ((-p) - v);
    e += t.l - pe;
    float corr = (s + e) / (2.0f * y);
    return ds_norm(y, corr);
}
__device__ __forceinline__ DS ds_log(DS a) {
    int ix = __float_as_int(a.h);
    int e = ((ix >> 23) & 0xFF) - 127;
    float sc = __int_as_float((127 - e) << 23);
    float mh = a.h * sc;
    float ml = a.l * sc;
    if (mh > 1.41421356f) { mh *= 0.5f; ml *= 0.5f; e += 1; }
    DS r = ds_norm(mh - 1.0f, ml);
    DS den = ds_add({2.0f, 0.0f}, r);
    DS s = ds_div(r, den);
    float z = s.h * s.h;
    float c = fmaf(z, 0.15384615f, 0.18181818f);
    c = fmaf(z, c, 0.22222222f);
    c = fmaf(z, c, 0.28571429f);
    c = fmaf(z, c, 0.4f);
    c = fmaf(z, c, 0.66666667f);
    c *= z;
    DS logm = ds_add({2.0f * s.h, 2.0f * s.l}, {s.h * c, 0.0f});
    float fe = (float)e;
    DS elog2 = {fe * 0.693145751953125f, fe * 1.4286068203094172e-06f};
    return ds_add(elog2, logm);
}

// ---------------- 1. fused prep: grid lift (blocks 0..63) + T (block 64) ----------------
__global__ __launch_bounds__(256) void k_prep(const float* __restrict__ ctrl) {
    if (blockIdx.x < 64) {
        int n = blockIdx.x*256 + threadIdx.x;
        int x = n & (OUT_W-1), y = n >> 8;
        float gx = ((float)x + 0.5f) * (1.0f/256.0f);  // exact
        float gy = ((float)y + 0.5f) * (1.0f/64.0f);   // exact
        g_glift[0*NPIX+n] = 1.0f;
        g_glift[1*NPIX+n] = gx;
        g_glift[2*NPIX+n] = gy;

        const DS EPS = {1e-6f, -1.1686097e-14f};
        #pragma unroll 4
        for (int k = 0; k < KPTS; ++k) {
            constexpr double step = (0.95 - 0.05) / 9.0;
            int j = (k < KPTS/2) ? k : (k - KPTS/2);
            double cxd = (j == 9) ? 0.95 : 0.05 + (double)j * step;
            double cyd = (k < KPTS/2) ? 0.05 : 0.95;
            float cxh = (float)cxd, cxl = (float)(cxd - (double)cxh);
            float cyh = (float)cyd, cyl = (float)(cyd - (double)cyh);
            DS dx = ds_add({gx, 0.0f}, {-cxh, -cxl});
            DS dy = ds_add({gy, 0.0f}, {-cyh, -cyl});
            DS t  = ds_add(ds_mul(dx, dx), ds_mul(dy, dy));
            DS d  = ds_sqrt(t);
            DS lg = ds_log(ds_add(d, EPS));
            DS v  = ds_mul(ds_mul(d, d), lg);
            g_glift[(3+k)*NPIX+n] = v.h;
        }
    } else {
        // T = INV_DELTA @ [ctrl; 0] for all batches
        for (int idx = threadIdx.x; idx < BATCH*KP3*2; idx += 256) {
            int b = idx / (KP3*2);
            int t = idx - b*(KP3*2);
            int i = t >> 1, c = t & 1;
            float acc = 0.f;
            #pragma unroll
            for (int j = 0; j < KPTS; ++j)
                acc = fmaf(g_invmat.m[i*KP3+j], ctrl[b*KPTS*2 + j*2 + c], acc);
            g_T[idx] = acc;
        }
    }
}

// ---------------- 2. grid eval + bilinear sampling ----------------
__global__ __launch_bounds__(OUT_W) void k_sample(const float* __restrict__ X,
                                                  float* __restrict__ out) {
    int y  = blockIdx.x;           // 0..63
    int b0 = blockIdx.y * BG;      // batch group
    int x  = threadIdx.x;          // 0..255
    int n  = y*OUT_W + x;

    __shared__ float2 Ts[BG*KP3];
    {
        const float2* gT2 = (const float2*)(g_T + b0*KP3*2);
        for (int t = threadIdx.x; t < BG*KP3; t += blockDim.x)
            Ts[t] = gT2[t];
    }

    float gl[KP3];
    #pragma unroll
    for (int i = 0; i < KP3; ++i) gl[i] = g_glift[i*NPIX + n];
    __syncthreads();

    #pragma unroll
    for (int bb = 0; bb < BG; ++bb) {
        int b = b0 + bb;
        const float2* tb = &Ts[bb*KP3];
        float gpx = 0.f, gpy = 0.f;
        #pragma unroll
        for (int i = 0; i < KP3; ++i) {
            float2 t2 = tb[i];
            gpx = fmaf(gl[i], t2.x, gpx);
            gpy = fmaf(gl[i], t2.y, gpy);
        }
        float Gx = fminf(fmaxf((float)IN_W * gpx, 0.f), (float)(IN_W-2));
        float Gy = fminf(fmaxf((float)IN_H * gpy, 0.f), (float)(IN_H-2));
        float fx0 = floorf(Gx), fy0 = floorf(Gy);
        int x0 = (int)fx0, y0 = (int)fy0;

        const float* p0 = X + (((size_t)b*IN_H + y0)*IN_W + x0)*3;
        const float* p1 = p0 + IN_W*3;

        float ax = Gx - fx0, bx = fx0 + 1.f - Gx;
        float ay = Gy - fy0, by = fy0 + 1.f - Gy;
        float w00 = bx*by, w01 = bx*ay, w10 = ax*by, w11 = ax*ay;

        float i00x=p0[0], i00y=p0[1], i00z=p0[2];
        float i10x=p0[3], i10y=p0[4], i10z=p0[5];
        float i01x=p1[0], i01y=p1[1], i01z=p1[2];
        float i11x=p1[3], i11y=p1[4], i11z=p1[5];

        float* o = out + (((size_t)b*OUT_H + y)*OUT_W + x)*3;
        o[0] = w00*i00x + w01*i01x + w10*i10x + w11*i11x;
        o[1] = w00*i00y + w01*i01y + w10*i10y + w11*i11y;
        o[2] = w00*i00z + w01*i01z + w10*i10z + w11*i11z;
    }
}

extern "C" void kernel_launch(void* const* d_in, const int* in_sizes, int n_in,
                              void* d_out, int out_size) {
    const float* X    = (const float*)d_in[0];
    const float* ctrl = (const float*)d_in[1];
    if (n_in >= 2 && in_sizes[0] == BATCH*KPTS*2) {   // defensive order swap
        X    = (const float*)d_in[1];
        ctrl = (const float*)d_in[0];
    }
    float* out = (float*)d_out;

    k_prep<<<65, 256>>>(ctrl);
    dim3 grid(OUT_H, BATCH/BG);
    k_sample<<<grid, OUT_W>>>(X, out);
}

// round 5
// speedup vs baseline: 6.1288x; 1.3392x over previous
#include <cuda_runtime.h>
#include <math.h>

#define KPTS 20
#define KP3  23
#define OUT_H 64
#define OUT_W 256
#define NPIX (OUT_H*OUT_W)   // 16384
#define BATCH 128
#define IN_H 128
#define IN_W 512
#define BG 4                 // batches per block in sampler

__device__ float g_glift[KP3*NPIX];   // transposed: [i][n]
__device__ float g_T[BATCH*KP3*2];    // [b][i][c]

// ===================== compile-time INV_DELTA (constexpr f64) =====================
__host__ __device__ constexpr double cpt_x(int k) {
    int j = (k < KPTS/2) ? k : (k - KPTS/2);
    double step = (0.95 - 0.05) / 9.0;
    return (j == 9) ? 0.95 : 0.05 + (double)j * step;
}
__host__ __device__ constexpr double cpt_y(int k) { return (k < KPTS/2) ? 0.05 : 0.95; }

constexpr double csqrt(double x) {
    double y = (x > 1.0) ? x : 1.0;
    for (int i = 0; i < 40; ++i) y = 0.5 * (y + x / y);
    return y;
}
constexpr double clog(double x) {
    double r = csqrt(csqrt(x));
    double s = (r - 1.0) / (r + 1.0);
    double z = s * s;
    double sum = 0.0, term = s;
    for (int n = 0; n < 26; ++n) {
        sum += term / (double)(2*n + 1);
        term *= z;
    }
    return 8.0 * sum;
}

struct InvMat { float m[KP3*KP3]; };

constexpr InvMat make_inv() {
    double A[KP3][2*KP3] = {};
    for (int r = 0; r < KP3; ++r)
        for (int c = 0; c < KP3; ++c) {
            double v = 0.0;
            if (r < KPTS) {
                if (c == 0) v = 1.0;
                else if (c == 1) v = cpt_x(r);
                else if (c == 2) v = cpt_y(r);
                else {
                    int k2 = c - 3;
                    if (r == k2) v = 0.0;
                    else {
                        double dx = cpt_x(r) - cpt_x(k2);
                        double dy = cpt_y(r) - cpt_y(k2);
                        double d = csqrt(dx*dx + dy*dy);
                        v = d*d*clog(d);
                    }
                }
            } else if (r == 20) { v = (c >= 3) ? cpt_x(c-3) : 0.0; }
            else if (r == 21)   { v = (c >= 3) ? cpt_y(c-3) : 0.0; }
            else                { v = (c >= 3) ? 1.0 : 0.0; }
            A[r][c] = v;
            A[r][KP3 + c] = (r == c) ? 1.0 : 0.0;
        }
    for (int p = 0; p < KP3; ++p) {
        int best = p; double bv = A[p][p] < 0 ? -A[p][p] : A[p][p];
        for (int r = p+1; r < KP3; ++r) {
            double v = A[r][p] < 0 ? -A[r][p] : A[r][p];
            if (v > bv) { bv = v; best = r; }
        }
        if (best != p)
            for (int c = 0; c < 2*KP3; ++c) {
                double t = A[p][c]; A[p][c] = A[best][c]; A[best][c] = t;
            }
        double ip = 1.0 / A[p][p];
        for (int c = 0; c < 2*KP3; ++c) A[p][c] *= ip;
        for (int r = 0; r < KP3; ++r) {
            if (r == p) continue;
            double f = A[r][p];
            for (int c = 0; c < 2*KP3; ++c) A[r][c] -= f * A[p][c];
        }
    }
    InvMat out{};
    for (int r = 0; r < KP3; ++r)
        for (int c = 0; c < KP3; ++c)
            out.m[r*KP3+c] = (float)A[r][KP3+c];
    return out;
}

__device__ constexpr InvMat g_invmat = make_inv();

// ======================= double-single (float-float) helpers =======================
struct DS { float h, l; };

__device__ __forceinline__ DS ds_norm(float h, float l) {
    float s = h + l;
    float e = l - (s - h);
    return {s, e};
}
__device__ __forceinline__ DS ds_add(DS a, DS b) {
    float s = a.h + b.h;
    float v = s - a.h;
    float e = (a.h - (s - v)) + (b.h - v);
    e += a.l + b.l;
    return ds_norm(s, e);
}
__device__ __forceinline__ DS ds_mul(DS a, DS b) {
    float p = a.h * b.h;
    float e = fmaf(a.h, b.h, -p);
    e = fmaf(a.h, b.l, e);
    e = fmaf(a.l, b.h, e);
    return ds_norm(p, e);
}
__device__ __forceinline__ DS ds_div(DS a, DS b) {
    float q = a.h / b.h;
    float p = q * b.h;
    float pe = fmaf(q, b.h, -p);
    float s = a.h - p;
    float v = s - a.h;
    float e = (a.h - (s - v)) + ((-p) - v);
    e += a.l - pe - q * b.l;
    float ql = (s + e) / b.h;
    return ds_norm(q, ql);
}
__device__ __forceinline__ DS ds_sqrt(DS t) {
    float y = sqrtf(t.h);
    float p = y * y;
    float pe = fmaf(y, y, -p);
    float s = t.h - p;
    float v = s - t.h;
    float e = (t.h - (s - v)) + ((-p) - v);
    e += t.l - pe;
    float corr = (s + e) / (2.0f * y);
    return ds_norm(y, corr);
}
__device__ __forceinline__ DS ds_log(DS a) {
    int ix = __float_as_int(a.h);
    int e = ((ix >> 23) & 0xFF) - 127;
    float sc = __int_as_float((127 - e) << 23);
    float mh = a.h * sc;
    float ml = a.l * sc;
    if (mh > 1.41421356f) { mh *= 0.5f; ml *= 0.5f; e += 1; }
    DS r = ds_norm(mh - 1.0f, ml);
    DS den = ds_add({2.0f, 0.0f}, r);
    DS s = ds_div(r, den);
    float z = s.h * s.h;
    float c = fmaf(z, 0.15384615f, 0.18181818f);
    c = fmaf(z, c, 0.22222222f);
    c = fmaf(z, c, 0.28571429f);
    c = fmaf(z, c, 0.4f);
    c = fmaf(z, c, 0.66666667f);
    c *= z;
    DS logm = ds_add({2.0f * s.h, 2.0f * s.l}, {s.h * c, 0.0f});
    float fe = (float)e;
    DS elog2 = {fe * 0.693145751953125f, fe * 1.4286068203094172e-06f};
    return ds_add(elog2, logm);
}

// ---------- 1. fully parallel prep: one thread per (pixel, k) RBF ----------
// blocks [0, 1280):        RBF rows       (NPIX*KPTS items)
// blocks [1280, 1472):     affine rows    (NPIX*3 items)
// blocks [1472, 1495):     T coefficients (BATCH*KP3*2 = 5888 items)
#define PREP_RBF_BLOCKS  (NPIX*KPTS/256)          // 1280
#define PREP_AFF_BLOCKS  (NPIX*3/256)             // 192
#define PREP_T_BLOCKS    ((BATCH*KP3*2 + 255)/256) // 23
#define PREP_BLOCKS      (PREP_RBF_BLOCKS + PREP_AFF_BLOCKS + PREP_T_BLOCKS)

__global__ __launch_bounds__(256) void k_prep(const float* __restrict__ ctrl) {
    int blk = blockIdx.x;
    if (blk < PREP_RBF_BLOCKS) {
        int id = blk*256 + threadIdx.x;
        int n = id & (NPIX-1);
        int k = id >> 14;                       // NPIX = 2^14
        int x = n & (OUT_W-1), y = n >> 8;
        float gx = ((float)x + 0.5f) * (1.0f/256.0f);
        float gy = ((float)y + 0.5f) * (1.0f/64.0f);

        constexpr double step = (0.95 - 0.05) / 9.0;
        int j = (k < KPTS/2) ? k : (k - KPTS/2);
        double cxd = (j == 9) ? 0.95 : 0.05 + (double)j * step;
        double cyd = (k < KPTS/2) ? 0.05 : 0.95;
        float cxh = (float)cxd, cxl = (float)(cxd - (double)cxh);
        float cyh = (float)cyd, cyl = (float)(cyd - (double)cyh);

        const DS EPS = {1e-6f, -1.1686097e-14f};
        DS dx = ds_add({gx, 0.0f}, {-cxh, -cxl});
        DS dy = ds_add({gy, 0.0f}, {-cyh, -cyl});
        DS t  = ds_add(ds_mul(dx, dx), ds_mul(dy, dy));
        DS d  = ds_sqrt(t);
        DS lg = ds_log(ds_add(d, EPS));
        DS v  = ds_mul(ds_mul(d, d), lg);
        g_glift[(3+k)*NPIX + n] = v.h;
    } else if (blk < PREP_RBF_BLOCKS + PREP_AFF_BLOCKS) {
        int id = (blk - PREP_RBF_BLOCKS)*256 + threadIdx.x;   // < NPIX*3
        int n = id & (NPIX-1);
        int row = id >> 14;                                   // 0..2
        int x = n & (OUT_W-1), y = n >> 8;
        float val = 1.0f;
        if (row == 1) val = ((float)x + 0.5f) * (1.0f/256.0f);
        if (row == 2) val = ((float)y + 0.5f) * (1.0f/64.0f);
        g_glift[row*NPIX + n] = val;
    } else {
        int idx = (blk - PREP_RBF_BLOCKS - PREP_AFF_BLOCKS)*256 + threadIdx.x;
        if (idx < BATCH*KP3*2) {
            int b = idx / (KP3*2);
            int t = idx - b*(KP3*2);
            int i = t >> 1, c = t & 1;
            float acc = 0.f;
            #pragma unroll
            for (int j2 = 0; j2 < KPTS; ++j2)
                acc = fmaf(g_invmat.m[i*KP3+j2], __ldg(&ctrl[b*KPTS*2 + j2*2 + c]), acc);
            g_T[idx] = acc;
        }
    }
}

// ---------- 2. sampler: grid eval + channel-split redistributed gather ----------
__global__ __launch_bounds__(OUT_W) void k_sample(const float* __restrict__ X,
                                                  float* __restrict__ out) {
    int y    = blockIdx.x;            // 0..63
    int b0   = blockIdx.y * BG;       // batch group
    int tid  = threadIdx.x;           // 0..255 (output x)
    int warp = tid >> 5, lane = tid & 31;
    int n    = y*OUT_W + tid;

    __shared__ float2 Ts[BG*KP3];
    __shared__ float4 sw[OUT_W];      // per-pixel bilinear weights
    __shared__ int    sb[OUT_W];      // per-pixel input base offset (elements)
    {
        const float2* gT2 = (const float2*)(g_T + b0*KP3*2);
        for (int t = tid; t < BG*KP3; t += blockDim.x)
            Ts[t] = gT2[t];
    }

    float gl[KP3];
    #pragma unroll
    for (int i = 0; i < KP3; ++i) gl[i] = g_glift[i*NPIX + n];
    __syncthreads();

    #pragma unroll
    for (int bb = 0; bb < BG; ++bb) {
        int b = b0 + bb;
        const float2* tb = &Ts[bb*KP3];
        float gpx = 0.f, gpy = 0.f;
        #pragma unroll
        for (int i = 0; i < KP3; ++i) {
            float2 t2 = tb[i];
            gpx = fmaf(gl[i], t2.x, gpx);
            gpy = fmaf(gl[i], t2.y, gpy);
        }
        float Gx = fminf(fmaxf((float)IN_W * gpx, 0.f), (float)(IN_W-2));
        float Gy = fminf(fmaxf((float)IN_H * gpy, 0.f), (float)(IN_H-2));
        float fx0 = floorf(Gx), fy0 = floorf(Gy);
        int x0 = (int)fx0, y0 = (int)fy0;

        float ax = Gx - fx0, bx = fx0 + 1.f - Gx;
        float ay = Gy - fy0, by = fy0 + 1.f - Gy;
        // order: {w00, w01, w10, w11} pairing {I00, I01, I10, I11}
        sw[tid] = make_float4(bx*by, bx*ay, ax*by, ax*ay);
        sb[tid] = ((b*IN_H + y0)*IN_W + x0)*3;
        __syncwarp();

        // redistribute: 96 (pixel,channel) items over 3 passes of 32 lanes
        size_t obase = ((size_t)(b*OUT_H + y)*OUT_W + warp*32)*3;
        #pragma unroll
        for (int pass = 0; pass < 3; ++pass) {
            int i = pass*32 + lane;          // 0..95
            int p = i / 3;                    // pixel within warp slab
            int c = i - p*3;                  // channel
            float4 w = sw[warp*32 + p];
            int ba = sb[warp*32 + p] + c;
            float v00 = __ldg(X + ba);
            float v10 = __ldg(X + ba + 3);
            float v01 = __ldg(X + ba + IN_W*3);
            float v11 = __ldg(X + ba + IN_W*3 + 3);
            out[obase + i] = w.x*v00 + w.y*v01 + w.z*v10 + w.w*v11;
        }
        __syncwarp();
    }
}

extern "C" void kernel_launch(void* const* d_in, const int* in_sizes, int n_in,
                              void* d_out, int out_size) {
    const float* X    = (const float*)d_in[0];
    const float* ctrl = (const float*)d_in[1];
    if (n_in >= 2 && in_sizes[0] == BATCH*KPTS*2) {   // defensive order swap
        X    = (const float*)d_in[1];
        ctrl = (const float*)d_in[0];
    }
    float* out = (float*)d_out;

    k_prep<<<PREP_BLOCKS, 256>>>(ctrl);
    dim3 grid(OUT_H, BATCH/BG);
    k_sample<<<grid, OUT_W>>>(X, out);
}

// round 6
// speedup vs baseline: 6.4521x; 1.0528x over previous
#include <cuda_runtime.h>
#include <math.h>

#define KPTS 20
#define KP3  23
#define OUT_H 64
#define OUT_W 256
#define NPIX (OUT_H*OUT_W)   // 16384
#define BATCH 128
#define IN_H 128
#define IN_W 512
#define BG 8                 // batches per block in sampler

__device__ float g_glift[KP3*NPIX];   // transposed: [i][n]
__device__ float g_T[BATCH*KP3*2];    // [b][i][c]

// ===================== compile-time INV_DELTA (constexpr f64) =====================
__host__ __device__ constexpr double cpt_x(int k) {
    int j = (k < KPTS/2) ? k : (k - KPTS/2);
    double step = (0.95 - 0.05) / 9.0;
    return (j == 9) ? 0.95 : 0.05 + (double)j * step;
}
__host__ __device__ constexpr double cpt_y(int k) { return (k < KPTS/2) ? 0.05 : 0.95; }

constexpr double csqrt(double x) {
    double y = (x > 1.0) ? x : 1.0;
    for (int i = 0; i < 40; ++i) y = 0.5 * (y + x / y);
    return y;
}
constexpr double clog(double x) {
    double r = csqrt(csqrt(x));
    double s = (r - 1.0) / (r + 1.0);
    double z = s * s;
    double sum = 0.0, term = s;
    for (int n = 0; n < 26; ++n) {
        sum += term / (double)(2*n + 1);
        term *= z;
    }
    return 8.0 * sum;
}

struct InvMat { float m[KP3*KP3]; };

constexpr InvMat make_inv() {
    double A[KP3][2*KP3] = {};
    for (int r = 0; r < KP3; ++r)
        for (int c = 0; c < KP3; ++c) {
            double v = 0.0;
            if (r < KPTS) {
                if (c == 0) v = 1.0;
                else if (c == 1) v = cpt_x(r);
                else if (c == 2) v = cpt_y(r);
                else {
                    int k2 = c - 3;
                    if (r == k2) v = 0.0;
                    else {
                        double dx = cpt_x(r) - cpt_x(k2);
                        double dy = cpt_y(r) - cpt_y(k2);
                        double d = csqrt(dx*dx + dy*dy);
                        v = d*d*clog(d);
                    }
                }
            } else if (r == 20) { v = (c >= 3) ? cpt_x(c-3) : 0.0; }
            else if (r == 21)   { v = (c >= 3) ? cpt_y(c-3) : 0.0; }
            else                { v = (c >= 3) ? 1.0 : 0.0; }
            A[r][c] = v;
            A[r][KP3 + c] = (r == c) ? 1.0 : 0.0;
        }
    for (int p = 0; p < KP3; ++p) {
        int best = p; double bv = A[p][p] < 0 ? -A[p][p] : A[p][p];
        for (int r = p+1; r < KP3; ++r) {
            double v = A[r][p] < 0 ? -A[r][p] : A[r][p];
            if (v > bv) { bv = v; best = r; }
        }
        if (best != p)
            for (int c = 0; c < 2*KP3; ++c) {
                double t = A[p][c]; A[p][c] = A[best][c]; A[best][c] = t;
            }
        double ip = 1.0 / A[p][p];
        for (int c = 0; c < 2*KP3; ++c) A[p][c] *= ip;
        for (int r = 0; r < KP3; ++r) {
            if (r == p) continue;
            double f = A[r][p];
            for (int c = 0; c < 2*KP3; ++c) A[r][c] -= f * A[p][c];
        }
    }
    InvMat out{};
    for (int r = 0; r < KP3; ++r)
        for (int c = 0; c < KP3; ++c)
            out.m[r*KP3+c] = (float)A[r][KP3+c];
    return out;
}

__device__ constexpr InvMat g_invmat = make_inv();

// ======================= double-single (float-float) helpers =======================
struct DS { float h, l; };

__device__ __forceinline__ DS ds_norm(float h, float l) {
    float s = h + l;
    float e = l - (s - h);
    return {s, e};
}
__device__ __forceinline__ DS ds_add(DS a, DS b) {
    float s = a.h + b.h;
    float v = s - a.h;
    float e = (a.h - (s - v)) + (b.h - v);
    e += a.l + b.l;
    return ds_norm(s, e);
}
__device__ __forceinline__ DS ds_mul(DS a, DS b) {
    float p = a.h * b.h;
    float e = fmaf(a.h, b.h, -p);
    e = fmaf(a.h, b.l, e);
    e = fmaf(a.l, b.h, e);
    return ds_norm(p, e);
}
__device__ __forceinline__ DS ds_div(DS a, DS b) {
    float q = a.h / b.h;
    float p = q * b.h;
    float pe = fmaf(q, b.h, -p);
    float s = a.h - p;
    float v = s - a.h;
    float e = (a.h - (s - v)) + ((-p) - v);
    e += a.l - pe - q * b.l;
    float ql = (s + e) / b.h;
    return ds_norm(q, ql);
}
__device__ __forceinline__ DS ds_sqrt(DS t) {
    float y = sqrtf(t.h);
    float p = y * y;
    float pe = fmaf(y, y, -p);
    float s = t.h - p;
    float v = s - t.h;
    float e = (t.h - (s - v)) + ((-p) - v);
    e += t.l - pe;
    float corr = (s + e) / (2.0f * y);
    return ds_norm(y, corr);
}
__device__ __forceinline__ DS ds_log(DS a) {
    int ix = __float_as_int(a.h);
    int e = ((ix >> 23) & 0xFF) - 127;
    float sc = __int_as_float((127 - e) << 23);
    float mh = a.h * sc;
    float ml = a.l * sc;
    if (mh > 1.41421356f) { mh *= 0.5f; ml *= 0.5f; e += 1; }
    DS r = ds_norm(mh - 1.0f, ml);
    DS den = ds_add({2.0f, 0.0f}, r);
    DS s = ds_div(r, den);
    float z = s.h * s.h;
    float c = fmaf(z, 0.15384615f, 0.18181818f);
    c = fmaf(z, c, 0.22222222f);
    c = fmaf(z, c, 0.28571429f);
    c = fmaf(z, c, 0.4f);
    c = fmaf(z, c, 0.66666667f);
    c *= z;
    DS logm = ds_add({2.0f * s.h, 2.0f * s.l}, {s.h * c, 0.0f});
    float fe = (float)e;
    DS elog2 = {fe * 0.693145751953125f, fe * 1.4286068203094172e-06f};
    return ds_add(elog2, logm);
}

// ---------- 1. fully parallel prep: one thread per (pixel, k) RBF ----------
#define PREP_RBF_BLOCKS  (NPIX*KPTS/256)           // 1280
#define PREP_AFF_BLOCKS  (NPIX*3/256)              // 192
#define PREP_T_BLOCKS    ((BATCH*KP3*2 + 255)/256) // 23
#define PREP_BLOCKS      (PREP_RBF_BLOCKS + PREP_AFF_BLOCKS + PREP_T_BLOCKS)

__global__ __launch_bounds__(256) void k_prep(const float* __restrict__ ctrl) {
    int blk = blockIdx.x;
    if (blk < PREP_RBF_BLOCKS) {
        int id = blk*256 + threadIdx.x;
        int n = id & (NPIX-1);
        int k = id >> 14;                       // NPIX = 2^14
        int x = n & (OUT_W-1), y = n >> 8;
        float gx = ((float)x + 0.5f) * (1.0f/256.0f);
        float gy = ((float)y + 0.5f) * (1.0f/64.0f);

        constexpr double step = (0.95 - 0.05) / 9.0;
        int j = (k < KPTS/2) ? k : (k - KPTS/2);
        double cxd = (j == 9) ? 0.95 : 0.05 + (double)j * step;
        double cyd = (k < KPTS/2) ? 0.05 : 0.95;
        float cxh = (float)cxd, cxl = (float)(cxd - (double)cxh);
        float cyh = (float)cyd, cyl = (float)(cyd - (double)cyh);

        const DS EPS = {1e-6f, -1.1686097e-14f};
        DS dx = ds_add({gx, 0.0f}, {-cxh, -cxl});
        DS dy = ds_add({gy, 0.0f}, {-cyh, -cyl});
        DS t  = ds_add(ds_mul(dx, dx), ds_mul(dy, dy));
        DS d  = ds_sqrt(t);
        DS lg = ds_log(ds_add(d, EPS));
        DS v  = ds_mul(ds_mul(d, d), lg);
        g_glift[(3+k)*NPIX + n] = v.h;
    } else if (blk < PREP_RBF_BLOCKS + PREP_AFF_BLOCKS) {
        int id = (blk - PREP_RBF_BLOCKS)*256 + threadIdx.x;
        int n = id & (NPIX-1);
        int row = id >> 14;
        int x = n & (OUT_W-1), y = n >> 8;
        float val = 1.0f;
        if (row == 1) val = ((float)x + 0.5f) * (1.0f/256.0f);
        if (row == 2) val = ((float)y + 0.5f) * (1.0f/64.0f);
        g_glift[row*NPIX + n] = val;
    } else {
        int idx = (blk - PREP_RBF_BLOCKS - PREP_AFF_BLOCKS)*256 + threadIdx.x;
        if (idx < BATCH*KP3*2) {
            int b = idx / (KP3*2);
            int t = idx - b*(KP3*2);
            int i = t >> 1, c = t & 1;
            float acc = 0.f;
            #pragma unroll
            for (int j2 = 0; j2 < KPTS; ++j2)
                acc = fmaf(g_invmat.m[i*KP3+j2], __ldg(&ctrl[b*KPTS*2 + j2*2 + c]), acc);
            g_T[idx] = acc;
        }
    }
}

// ---------- 2. sampler: coords precomputed for all BG, shuffle-fed gather ----------
__global__ __launch_bounds__(OUT_W) void k_sample(const float* __restrict__ X,
                                                  float* __restrict__ out) {
    int y    = blockIdx.x;            // 0..63
    int b0   = blockIdx.y * BG;       // batch group
    int tid  = threadIdx.x;           // 0..255 (output x, = pixel owner)
    int warp = tid >> 5, lane = tid & 31;
    int n    = y*OUT_W + tid;

    __shared__ float2 Ts[BG*KP3];
    {
        const float2* gT2 = (const float2*)(g_T + b0*KP3*2);
        for (int t = tid; t < BG*KP3; t += blockDim.x)
            Ts[t] = gT2[t];
    }

    float gl[KP3];
    #pragma unroll
    for (int i = 0; i < KP3; ++i) gl[i] = g_glift[i*NPIX + n];
    __syncthreads();

    // phase 1: clamped sampling coords for all BG batches (gl dies after this)
    float cgx[BG], cgy[BG];
    #pragma unroll
    for (int bb = 0; bb < BG; ++bb) {
        const float2* tb = &Ts[bb*KP3];
        float gpx = 0.f, gpy = 0.f;
        #pragma unroll
        for (int i = 0; i < KP3; ++i) {
            float2 t2 = tb[i];
            gpx = fmaf(gl[i], t2.x, gpx);
            gpy = fmaf(gl[i], t2.y, gpy);
        }
        cgx[bb] = fminf(fmaxf((float)IN_W * gpx, 0.f), (float)(IN_W-2));
        cgy[bb] = fminf(fmaxf((float)IN_H * gpy, 0.f), (float)(IN_H-2));
    }

    // phase 2: gather, (pixel,channel) work items fed by shuffles
    #pragma unroll
    for (int bb = 0; bb < BG; ++bb) {
        int b = b0 + bb;
        float myGx = cgx[bb], myGy = cgy[bb];
        size_t obase = ((size_t)(b*OUT_H + y)*OUT_W + warp*32)*3;
        #pragma unroll
        for (int pass = 0; pass < 3; ++pass) {
            int i = pass*32 + lane;           // 0..95
            int p = i / 3;                     // source pixel (lane) in this warp
            int c = i - p*3;                   // channel
            float Gx = __shfl_sync(0xFFFFFFFFu, myGx, p);
            float Gy = __shfl_sync(0xFFFFFFFFu, myGy, p);
            float fx0 = floorf(Gx), fy0 = floorf(Gy);
            int x0 = (int)fx0, y0 = (int)fy0;
            float ax = Gx - fx0, bx = fx0 + 1.f - Gx;
            float ay = Gy - fy0, by = fy0 + 1.f - Gy;
            int ba = ((b*IN_H + y0)*IN_W + x0)*3 + c;
            float v00 = __ldg(X + ba);
            float v10 = __ldg(X + ba + 3);
            float v01 = __ldg(X + ba + IN_W*3);
            float v11 = __ldg(X + ba + IN_W*3 + 3);
            out[obase + i] = (bx*by)*v00 + (bx*ay)*v01 + (ax*by)*v10 + (ax*ay)*v11;
        }
    }
}

extern "C" void kernel_launch(void* const* d_in, const int* in_sizes, int n_in,
                              void* d_out, int out_size) {
    const float* X    = (const float*)d_in[0];
    const float* ctrl = (const float*)d_in[1];
    if (n_in >= 2 && in_sizes[0] == BATCH*KPTS*2) {   // defensive order swap
        X    = (const float*)d_in[1];
        ctrl = (const float*)d_in[0];
    }
    float* out = (float*)d_out;

    k_prep<<<PREP_BLOCKS, 256>>>(ctrl);
    dim3 grid(OUT_H, BATCH/BG);
    k_sample<<<grid, OUT_W>>>(X, out);
}

// round 7
// speedup vs baseline: 7.1484x; 1.1079x over previous
#include <cuda_runtime.h>
#include <math.h>

#define KPTS 20
#define KP3  23
#define OUT_H 64
#define OUT_W 256
#define NPIX (OUT_H*OUT_W)   // 16384
#define BATCH 128
#define IN_H 128
#define IN_W 512
#define BG 4                 // batches per block in sampler

__device__ float g_glift[KP3*NPIX];   // transposed: [i][n]
__device__ float g_T[BATCH*KP3*2];    // [b][i][c]

// ===================== compile-time INV_DELTA (constexpr f64) =====================
__host__ __device__ constexpr double cpt_x(int k) {
    int j = (k < KPTS/2) ? k : (k - KPTS/2);
    double step = (0.95 - 0.05) / 9.0;
    return (j == 9) ? 0.95 : 0.05 + (double)j * step;
}
__host__ __device__ constexpr double cpt_y(int k) { return (k < KPTS/2) ? 0.05 : 0.95; }

constexpr double csqrt(double x) {
    double y = (x > 1.0) ? x : 1.0;
    for (int i = 0; i < 40; ++i) y = 0.5 * (y + x / y);
    return y;
}
constexpr double clog(double x) {
    double r = csqrt(csqrt(x));
    double s = (r - 1.0) / (r + 1.0);
    double z = s * s;
    double sum = 0.0, term = s;
    for (int n = 0; n < 26; ++n) {
        sum += term / (double)(2*n + 1);
        term *= z;
    }
    return 8.0 * sum;
}

struct InvMat { float m[KP3*KP3]; };

constexpr InvMat make_inv() {
    double A[KP3][2*KP3] = {};
    for (int r = 0; r < KP3; ++r)
        for (int c = 0; c < KP3; ++c) {
            double v = 0.0;
            if (r < KPTS) {
                if (c == 0) v = 1.0;
                else if (c == 1) v = cpt_x(r);
                else if (c == 2) v = cpt_y(r);
                else {
                    int k2 = c - 3;
                    if (r == k2) v = 0.0;
                    else {
                        double dx = cpt_x(r) - cpt_x(k2);
                        double dy = cpt_y(r) - cpt_y(k2);
                        double d = csqrt(dx*dx + dy*dy);
                        v = d*d*clog(d);
                    }
                }
            } else if (r == 20) { v = (c >= 3) ? cpt_x(c-3) : 0.0; }
            else if (r == 21)   { v = (c >= 3) ? cpt_y(c-3) : 0.0; }
            else                { v = (c >= 3) ? 1.0 : 0.0; }
            A[r][c] = v;
            A[r][KP3 + c] = (r == c) ? 1.0 : 0.0;
        }
    for (int p = 0; p < KP3; ++p) {
        int best = p; double bv = A[p][p] < 0 ? -A[p][p] : A[p][p];
        for (int r = p+1; r < KP3; ++r) {
            double v = A[r][p] < 0 ? -A[r][p] : A[r][p];
            if (v > bv) { bv = v; best = r; }
        }
        if (best != p)
            for (int c = 0; c < 2*KP3; ++c) {
                double t = A[p][c]; A[p][c] = A[best][c]; A[best][c] = t;
            }
        double ip = 1.0 / A[p][p];
        for (int c = 0; c < 2*KP3; ++c) A[p][c] *= ip;
        for (int r = 0; r < KP3; ++r) {
            if (r == p) continue;
            double f = A[r][p];
            for (int c = 0; c < 2*KP3; ++c) A[r][c] -= f * A[p][c];
        }
    }
    InvMat out{};
    for (int r = 0; r < KP3; ++r)
        for (int c = 0; c < KP3; ++c)
            out.m[r*KP3+c] = (float)A[r][KP3+c];
    return out;
}

__device__ constexpr InvMat g_invmat = make_inv();

// ======================= double-single (float-float) helpers =======================
struct DS { float h, l; };

__device__ __forceinline__ DS ds_norm(float h, float l) {
    float s = h + l;
    float e = l - (s - h);
    return {s, e};
}
__device__ __forceinline__ DS ds_add(DS a, DS b) {
    float s = a.h + b.h;
    float v = s - a.h;
    float e = (a.h - (s - v)) + (b.h - v);
    e += a.l + b.l;
    return ds_norm(s, e);
}
__device__ __forceinline__ DS ds_mul(DS a, DS b) {
    float p = a.h * b.h;
    float e = fmaf(a.h, b.h, -p);
    e = fmaf(a.h, b.l, e);
    e = fmaf(a.l, b.h, e);
    return ds_norm(p, e);
}
__device__ __forceinline__ DS ds_div(DS a, DS b) {
    float q = a.h / b.h;
    float p = q * b.h;
    float pe = fmaf(q, b.h, -p);
    float s = a.h - p;
    float v = s - a.h;
    float e = (a.h - (s - v)) + ((-p) - v);
    e += a.l - pe - q * b.l;
    float ql = (s + e) / b.h;
    return ds_norm(q, ql);
}
__device__ __forceinline__ DS ds_sqrt(DS t) {
    float y = sqrtf(t.h);
    float p = y * y;
    float pe = fmaf(y, y, -p);
    float s = t.h - p;
    float v = s - t.h;
    float e = (t.h - (s - v)) + ((-p) - v);
    e += t.l - pe;
    float corr = (s + e) / (2.0f * y);
    return ds_norm(y, corr);
}
__device__ __forceinline__ DS ds_log(DS a) {
    int ix = __float_as_int(a.h);
    int e = ((ix >> 23) & 0xFF) - 127;
    float sc = __int_as_float((127 - e) << 23);
    float mh = a.h * sc;
    float ml = a.l * sc;
    if (mh > 1.41421356f) { mh *= 0.5f; ml *= 0.5f; e += 1; }
    DS r = ds_norm(mh - 1.0f, ml);
    DS den = ds_add({2.0f, 0.0f}, r);
    DS s = ds_div(r, den);
    float z = s.h * s.h;
    float c = fmaf(z, 0.15384615f, 0.18181818f);
    c = fmaf(z, c, 0.22222222f);
    c = fmaf(z, c, 0.28571429f);
    c = fmaf(z, c, 0.4f);
    c = fmaf(z, c, 0.66666667f);
    c *= z;
    DS logm = ds_add({2.0f * s.h, 2.0f * s.l}, {s.h * c, 0.0f});
    float fe = (float)e;
    DS elog2 = {fe * 0.693145751953125f, fe * 1.4286068203094172e-06f};
    return ds_add(elog2, logm);
}

// ---------- 1. fully parallel prep: one thread per (pixel, k) RBF ----------
#define PREP_RBF_BLOCKS  (NPIX*KPTS/256)           // 1280
#define PREP_AFF_BLOCKS  (NPIX*3/256)              // 192
#define PREP_T_BLOCKS    ((BATCH*KP3*2 + 255)/256) // 23
#define PREP_BLOCKS      (PREP_RBF_BLOCKS + PREP_AFF_BLOCKS + PREP_T_BLOCKS)

__global__ __launch_bounds__(256) void k_prep(const float* __restrict__ ctrl) {
    int blk = blockIdx.x;
    if (blk < PREP_RBF_BLOCKS) {
        int id = blk*256 + threadIdx.x;
        int n = id & (NPIX-1);
        int k = id >> 14;                       // NPIX = 2^14
        int x = n & (OUT_W-1), y = n >> 8;
        float gx = ((float)x + 0.5f) * (1.0f/256.0f);
        float gy = ((float)y + 0.5f) * (1.0f/64.0f);

        constexpr double step = (0.95 - 0.05) / 9.0;
        int j = (k < KPTS/2) ? k : (k - KPTS/2);
        double cxd = (j == 9) ? 0.95 : 0.05 + (double)j * step;
        double cyd = (k < KPTS/2) ? 0.05 : 0.95;
        float cxh = (float)cxd, cxl = (float)(cxd - (double)cxh);
        float cyh = (float)cyd, cyl = (float)(cyd - (double)cyh);

        const DS EPS = {1e-6f, -1.1686097e-14f};
        DS dx = ds_add({gx, 0.0f}, {-cxh, -cxl});
        DS dy = ds_add({gy, 0.0f}, {-cyh, -cyl});
        DS t  = ds_add(ds_mul(dx, dx), ds_mul(dy, dy));
        DS d  = ds_sqrt(t);
        DS lg = ds_log(ds_add(d, EPS));
        DS v  = ds_mul(ds_mul(d, d), lg);
        g_glift[(3+k)*NPIX + n] = v.h;
    } else if (blk < PREP_RBF_BLOCKS + PREP_AFF_BLOCKS) {
        int id = (blk - PREP_RBF_BLOCKS)*256 + threadIdx.x;
        int n = id & (NPIX-1);
        int row = id >> 14;
        int x = n & (OUT_W-1), y = n >> 8;
        float val = 1.0f;
        if (row == 1) val = ((float)x + 0.5f) * (1.0f/256.0f);
        if (row == 2) val = ((float)y + 0.5f) * (1.0f/64.0f);
        g_glift[row*NPIX + n] = val;
    } else {
        int idx = (blk - PREP_RBF_BLOCKS - PREP_AFF_BLOCKS)*256 + threadIdx.x;
        if (idx < BATCH*KP3*2) {
            int b = idx / (KP3*2);
            int t = idx - b*(KP3*2);
            int i = t >> 1, c = t & 1;
            float acc = 0.f;
            #pragma unroll
            for (int j2 = 0; j2 < KPTS; ++j2)
                acc = fmaf(g_invmat.m[i*KP3+j2], __ldg(&ctrl[b*KPTS*2 + j2*2 + c]), acc);
            g_T[idx] = acc;
        }
    }
}

// ---------- 2. sampler: coords precomputed for BG batches, shuffle-fed gather ----------
__global__ __launch_bounds__(OUT_W, 4) void k_sample(const float* __restrict__ X,
                                                     float* __restrict__ out) {
    int y    = blockIdx.x;            // 0..63
    int b0   = blockIdx.y * BG;       // batch group
    int tid  = threadIdx.x;           // 0..255 (output x, = pixel owner)
    int warp = tid >> 5, lane = tid & 31;
    int n    = y*OUT_W + tid;

    __shared__ float2 Ts[BG*KP3];
    {
        const float2* gT2 = (const float2*)(g_T + b0*KP3*2);
        for (int t = tid; t < BG*KP3; t += blockDim.x)
            Ts[t] = gT2[t];
    }

    float gl[KP3];
    #pragma unroll
    for (int i = 0; i < KP3; ++i) gl[i] = g_glift[i*NPIX + n];
    __syncthreads();

    // phase 1: clamped sampling coords for all BG batches (gl dies after this)
    float cgx[BG], cgy[BG];
    #pragma unroll
    for (int bb = 0; bb < BG; ++bb) {
        const float2* tb = &Ts[bb*KP3];
        float gpx = 0.f, gpy = 0.f;
        #pragma unroll
        for (int i = 0; i < KP3; ++i) {
            float2 t2 = tb[i];
            gpx = fmaf(gl[i], t2.x, gpx);
            gpy = fmaf(gl[i], t2.y, gpy);
        }
        cgx[bb] = fminf(fmaxf((float)IN_W * gpx, 0.f), (float)(IN_W-2));
        cgy[bb] = fminf(fmaxf((float)IN_H * gpy, 0.f), (float)(IN_H-2));
    }

    // phase 2: gather, (pixel,channel) work items fed by shuffles
    #pragma unroll
    for (int bb = 0; bb < BG; ++bb) {
        int b = b0 + bb;
        float myGx = cgx[bb], myGy = cgy[bb];
        size_t obase = ((size_t)(b*OUT_H + y)*OUT_W + warp*32)*3;
        #pragma unroll
        for (int pass = 0; pass < 3; ++pass) {
            int i = pass*32 + lane;           // 0..95
            int p = i / 3;                     // source pixel (lane) in this warp
            int c = i - p*3;                   // channel
            float Gx = __shfl_sync(0xFFFFFFFFu, myGx, p);
            float Gy = __shfl_sync(0xFFFFFFFFu, myGy, p);
            float fx0 = floorf(Gx), fy0 = floorf(Gy);
            int x0 = (int)fx0, y0 = (int)fy0;
            float ax = Gx - fx0, bx = fx0 + 1.f - Gx;
            float ay = Gy - fy0, by = fy0 + 1.f - Gy;
            int ba = ((b*IN_H + y0)*IN_W + x0)*3 + c;
            float v00 = __ldg(X + ba);
            float v10 = __ldg(X + ba + 3);
            float v01 = __ldg(X + ba + IN_W*3);
            float v11 = __ldg(X + ba + IN_W*3 + 3);
            out[obase + i] = (bx*by)*v00 + (bx*ay)*v01 + (ax*by)*v10 + (ax*ay)*v11;
        }
    }
}

extern "C" void kernel_launch(void* const* d_in, const int* in_sizes, int n_in,
                              void* d_out, int out_size) {
    const float* X    = (const float*)d_in[0];
    const float* ctrl = (const float*)d_in[1];
    if (n_in >= 2 && in_sizes[0] == BATCH*KPTS*2) {   // defensive order swap
        X    = (const float*)d_in[1];
        ctrl = (const float*)d_in[0];
    }
    float* out = (float*)d_out;

    k_prep<<<PREP_BLOCKS, 256>>>(ctrl);
    dim3 grid(OUT_H, BATCH/BG);
    k_sample<<<grid, OUT_W>>>(X, out);
}